// round 1
// baseline (speedup 1.0000x reference)
#include <cuda_runtime.h>

// relu(X[131072,256] @ W[256,256]^T + b) , all fp32.
// Round 0: correct fp32 SGEMM baseline. BM=BN=128, BK=16, TM=TN=8, 256 thr.

#define BM 128
#define BN 128
#define BK 16
#define TM 8
#define TN 8
#define KDIM 256
#define NDIM 256

__global__ __launch_bounds__(256, 2)
void gemm_bias_relu_kernel(const float* __restrict__ X,
                           const float* __restrict__ W,
                           const float* __restrict__ bias,
                           float* __restrict__ out,
                           int Brows) {
    __shared__ float As[BK][BM];   // X tile, k-major (transposed on store)
    __shared__ float Bs[BK][BN];   // W tile, k-major

    const int bx = blockIdx.x;          // M tile index
    const int by = blockIdx.y;          // N tile index (0..1)
    const int tid = threadIdx.x;
    const int tx = tid & 15;            // 0..15 -> N micro-tile
    const int ty = tid >> 4;            // 0..15 -> M micro-tile

    const float* Xblk = X + (size_t)bx * BM * KDIM;
    const float* Wblk = W + (size_t)by * BN * KDIM;   // W is [N,K] row-major

    float acc[TM][TN];
    #pragma unroll
    for (int i = 0; i < TM; i++)
        #pragma unroll
        for (int j = 0; j < TN; j++) acc[i][j] = 0.0f;

    float ar[TM], br[TN];

    for (int kt = 0; kt < KDIM; kt += BK) {
        // ---- load tiles: 128 rows x 16 k each = 512 float4 per tile; 2 per thread
        #pragma unroll
        for (int l = 0; l < 2; l++) {
            int id = tid + l * 256;
            int r = id >> 2;            // row within tile (0..127)
            int c = id & 3;             // float4 slot within k (0..3)
            float4 vx = *(const float4*)(Xblk + (size_t)r * KDIM + kt + c * 4);
            As[c * 4 + 0][r] = vx.x;
            As[c * 4 + 1][r] = vx.y;
            As[c * 4 + 2][r] = vx.z;
            As[c * 4 + 3][r] = vx.w;
            float4 vw = *(const float4*)(Wblk + (size_t)r * KDIM + kt + c * 4);
            Bs[c * 4 + 0][r] = vw.x;
            Bs[c * 4 + 1][r] = vw.y;
            Bs[c * 4 + 2][r] = vw.z;
            Bs[c * 4 + 3][r] = vw.w;
        }
        __syncthreads();

        // ---- compute
        #pragma unroll
        for (int k = 0; k < BK; k++) {
            #pragma unroll
            for (int i = 0; i < TM; i++) ar[i] = As[k][ty * TM + i];
            #pragma unroll
            for (int j = 0; j < TN; j++) br[j] = Bs[k][tx * TN + j];
            #pragma unroll
            for (int i = 0; i < TM; i++)
                #pragma unroll
                for (int j = 0; j < TN; j++)
                    acc[i][j] = fmaf(ar[i], br[j], acc[i][j]);
        }
        __syncthreads();
    }

    // ---- epilogue: bias + relu, vectorized stores
    const int col0 = by * BN + tx * TN;
    float bv[TN];
    #pragma unroll
    for (int j = 0; j < TN; j++) bv[j] = bias[col0 + j];

    #pragma unroll
    for (int i = 0; i < TM; i++) {
        int row = bx * BM + ty * TM + i;
        float* orow = out + (size_t)row * NDIM + col0;
        float4 v0, v1;
        v0.x = fmaxf(acc[i][0] + bv[0], 0.0f);
        v0.y = fmaxf(acc[i][1] + bv[1], 0.0f);
        v0.z = fmaxf(acc[i][2] + bv[2], 0.0f);
        v0.w = fmaxf(acc[i][3] + bv[3], 0.0f);
        v1.x = fmaxf(acc[i][4] + bv[4], 0.0f);
        v1.y = fmaxf(acc[i][5] + bv[5], 0.0f);
        v1.z = fmaxf(acc[i][6] + bv[6], 0.0f);
        v1.w = fmaxf(acc[i][7] + bv[7], 0.0f);
        *(float4*)(orow + 0) = v0;
        *(float4*)(orow + 4) = v1;
    }
}

extern "C" void kernel_launch(void* const* d_in, const int* in_sizes, int n_in,
                              void* d_out, int out_size) {
    const float* X    = (const float*)d_in[0];   // [131072, 256]
    const float* W    = (const float*)d_in[1];   // [256, 256]
    const float* bias = (const float*)d_in[2];   // [256]
    float* out = (float*)d_out;                  // [131072, 256]

    const int Brows = in_sizes[0] / KDIM;        // 131072
    dim3 grid(Brows / BM, NDIM / BN);            // (1024, 2)
    gemm_bias_relu_kernel<<<grid, 256>>>(X, W, bias, out, Brows);
}

// round 3
// speedup vs baseline: 2.2770x; 2.2770x over previous
#include <cuda_runtime.h>
#include <cuda_bf16.h>
#include <cstdint>

// relu(X[131072,256] @ W[256,256]^T + b), fp32.
// Legacy tensor-core path (sm_80-compatible PTX only): mma.sync m16n8k16 bf16,
// 3-MMA hi/lo split for fp32-grade accuracy. No tcgen05 / TMA (harness ptxas
// targets plain sm_103, which rejects tcgen05.ld/st/wait).

#define KDIM 256
#define NDIM 256
#define BM   128
#define BN   256
#define KC   64
#define NCHUNK (KDIM / KC)

// ---- smem layout (bytes from dynamic base; tile bases 1024-aligned) ----
#define SM_BIAS  0          // 256 floats
#define SM_XSTG  1024       // staged fp32 X chunk: 128 rows x 64 f32 = 32KB
#define SM_BUF   33792      // 33*1024
#define OFF_AHI  0          // 128 rows x 128B = 16KB
#define OFF_ALO  16384
#define OFF_BHI  32768      // 256 rows x 128B = 32KB
#define OFF_BLO  65536
#define BUF_BYTES 98304     // 96KB per stage
#define SMEM_TOTAL (SM_BUF + 2 * BUF_BYTES)   // 230400 B

__device__ __forceinline__ uint32_t smem_u32(const void* p) {
    uint32_t a;
    asm("{ .reg .u64 t; cvta.to.shared.u64 t, %1; cvt.u32.u64 %0, t; }" : "=r"(a) : "l"(p));
    return a;
}

__device__ __forceinline__ void cp_async16(uint32_t dst, const void* src) {
    asm volatile("cp.async.ca.shared.global [%0], [%1], 16;" :: "r"(dst), "l"(src) : "memory");
}
__device__ __forceinline__ void cp_commit() {
    asm volatile("cp.async.commit_group;" ::: "memory");
}
__device__ __forceinline__ void cp_wait0() {
    asm volatile("cp.async.wait_group 0;" ::: "memory");
}

__device__ __forceinline__ void ldm_x4(uint32_t addr, uint32_t& r0, uint32_t& r1,
                                       uint32_t& r2, uint32_t& r3) {
    asm volatile("ldmatrix.sync.aligned.m8n8.x4.shared.b16 {%0,%1,%2,%3}, [%4];"
                 : "=r"(r0), "=r"(r1), "=r"(r2), "=r"(r3) : "r"(addr));
}

__device__ __forceinline__ void mma16816(float* c, const uint32_t* a, uint32_t b0, uint32_t b1) {
    asm volatile(
        "mma.sync.aligned.m16n8k16.row.col.f32.bf16.bf16.f32 "
        "{%0,%1,%2,%3}, {%4,%5,%6,%7}, {%8,%9}, {%0,%1,%2,%3};"
        : "+f"(c[0]), "+f"(c[1]), "+f"(c[2]), "+f"(c[3])
        : "r"(a[0]), "r"(a[1]), "r"(a[2]), "r"(a[3]), "r"(b0), "r"(b1));
}

// ---- W pre-split: fp32 -> bf16 hi + lo, row-major [N, K] ----
__device__ __nv_bfloat16 g_Whi[NDIM * KDIM];
__device__ __nv_bfloat16 g_Wlo[NDIM * KDIM];

__global__ void split_w_kernel(const float* __restrict__ W) {
    int i = blockIdx.x * 256 + threadIdx.x;
    float v = W[i];
    __nv_bfloat16 h = __float2bfloat16(v);
    g_Whi[i] = h;
    g_Wlo[i] = __float2bfloat16(v - __bfloat162float(h));
}

// ---- main kernel ----
__global__ __launch_bounds__(256, 1)
void gemm_hmma_kernel(const float* __restrict__ X,
                      const float* __restrict__ bias,
                      float* __restrict__ out) {
    extern __shared__ char sm[];
    const uint32_t smb = smem_u32(sm);
    const int tid  = threadIdx.x;
    const int wid  = tid >> 5;
    const int lane = tid & 31;
    const int bx   = blockIdx.x;

    const int wm = wid & 1;        // M half (0..1), 64 rows each
    const int wn = wid >> 1;       // N quarter (0..3), 64 cols each

    ((float*)(sm + SM_BIAS))[tid] = bias[tid];

    const float* Xblk = X + (size_t)bx * BM * KDIM;

    // per-thread cp.async coordinates
    const int xrow = tid >> 4, xc = tid & 15;      // X: 16 float4 per row
    const int brow = tid >> 3, bc = tid & 7;       // B: 8 16B per row

    // lane constants for ldmatrix addressing
    const uint32_t swx   = (uint32_t)(lane & 7) << 4;            // SW128 xor value
    const int a_mrow = wm * 64 + (lane & 7) + ((lane >> 3) & 1) * 8;  // + mb*16
    const uint32_t a_khalf = (uint32_t)(lane >> 4) * 16;
    const int b_nrow = wn * 64 + (lane & 7) + ((lane >> 4) ? 8 : 0);  // + ng*16
    const uint32_t b_khalf = (uint32_t)((lane >> 3) & 1) * 16;

    float acc[4][8][4];
    #pragma unroll
    for (int i = 0; i < 4; i++)
        #pragma unroll
        for (int j = 0; j < 8; j++)
            #pragma unroll
            for (int q = 0; q < 4; q++) acc[i][j][q] = 0.0f;

    // ---- prologue: prefetch chunk 0
    {
        #pragma unroll
        for (int it = 0; it < 8; it++) {
            int id = tid + it * 256;
            int r = id >> 4, c = id & 15;
            cp_async16(smb + SM_XSTG + (uint32_t)(r * 256 + c * 16),
                       Xblk + (size_t)r * KDIM + c * 4);
        }
        #pragma unroll
        for (int it = 0; it < 8; it++) {
            int id = tid + it * 256;
            int r = id >> 3, c = id & 7;
            uint32_t off = (uint32_t)(r * 128 + c * 16);
            uint32_t swo = off ^ ((off >> 3) & 0x70);
            cp_async16(smb + SM_BUF + OFF_BHI + swo, g_Whi + r * KDIM + c * 8);
            cp_async16(smb + SM_BUF + OFF_BLO + swo, g_Wlo + r * KDIM + c * 8);
        }
        cp_commit();
    }

    for (int kc = 0; kc < NCHUNK; kc++) {
        const uint32_t cur = smb + SM_BUF + (uint32_t)(kc & 1) * BUF_BYTES;
        const uint32_t nxt = smb + SM_BUF + (uint32_t)((kc & 1) ^ 1) * BUF_BYTES;

        cp_wait0();
        __syncthreads();              // X(kc) staged, B(kc) in cur; prior readers done

        // ---- convert staged fp32 X -> bf16 hi/lo into cur buffer (swizzled)
        #pragma unroll
        for (int it = 0; it < 8; it++) {
            int id = tid + it * 256;
            int r = id >> 4, c = id & 15;
            float4 v = *(const float4*)(sm + SM_XSTG + (uint32_t)(r * 256 + c * 16));
            __nv_bfloat16 h0 = __float2bfloat16(v.x);
            __nv_bfloat16 h1 = __float2bfloat16(v.y);
            __nv_bfloat16 h2 = __float2bfloat16(v.z);
            __nv_bfloat16 h3 = __float2bfloat16(v.w);
            __nv_bfloat16 l0 = __float2bfloat16(v.x - __bfloat162float(h0));
            __nv_bfloat16 l1 = __float2bfloat16(v.y - __bfloat162float(h1));
            __nv_bfloat16 l2 = __float2bfloat16(v.z - __bfloat162float(h2));
            __nv_bfloat16 l3 = __float2bfloat16(v.w - __bfloat162float(h3));
            uint2 hv, lv;
            hv.x = (uint32_t)__bfloat16_as_ushort(h0) | ((uint32_t)__bfloat16_as_ushort(h1) << 16);
            hv.y = (uint32_t)__bfloat16_as_ushort(h2) | ((uint32_t)__bfloat16_as_ushort(h3) << 16);
            lv.x = (uint32_t)__bfloat16_as_ushort(l0) | ((uint32_t)__bfloat16_as_ushort(l1) << 16);
            lv.y = (uint32_t)__bfloat16_as_ushort(l2) | ((uint32_t)__bfloat16_as_ushort(l3) << 16);
            uint32_t off = (uint32_t)(r * 128 + c * 8);
            uint32_t swo = off ^ ((off >> 3) & 0x70);
            *(uint2*)(sm + (cur - smb) + OFF_AHI + swo) = hv;
            *(uint2*)(sm + (cur - smb) + OFF_ALO + swo) = lv;
        }
        __syncthreads();              // A(kc) ready; XSTG free for reuse

        // ---- prefetch chunk kc+1 (overlaps with MMA below)
        if (kc + 1 < NCHUNK) {
            const int k0 = (kc + 1) * KC;
            #pragma unroll
            for (int it = 0; it < 8; it++) {
                int id = tid + it * 256;
                int r = id >> 4, c = id & 15;
                cp_async16(smb + SM_XSTG + (uint32_t)(r * 256 + c * 16),
                           Xblk + (size_t)r * KDIM + k0 + c * 4);
            }
            #pragma unroll
            for (int it = 0; it < 8; it++) {
                int id = tid + it * 256;
                int r = id >> 3, c = id & 7;
                uint32_t off = (uint32_t)(r * 128 + c * 16);
                uint32_t swo = off ^ ((off >> 3) & 0x70);
                cp_async16(nxt + OFF_BHI + swo, g_Whi + r * KDIM + k0 + c * 8);
                cp_async16(nxt + OFF_BLO + swo, g_Wlo + r * KDIM + k0 + c * 8);
            }
            cp_commit();
        }

        // ---- MMA over this chunk: 4 k16 steps x (hi*hi + hi*lo + lo*hi)
        #pragma unroll
        for (int kk = 0; kk < 4; kk++) {
            const uint32_t kof = (uint32_t)(kk * 32);
            uint32_t ahi[4][4], alo[4][4];
            #pragma unroll
            for (int mb = 0; mb < 4; mb++) {
                uint32_t rowoff = (uint32_t)((a_mrow + mb * 16) * 128);
                uint32_t dyn = (kof + a_khalf) ^ swx;
                ldm_x4(cur + OFF_AHI + rowoff + dyn,
                       ahi[mb][0], ahi[mb][1], ahi[mb][2], ahi[mb][3]);
                ldm_x4(cur + OFF_ALO + rowoff + dyn,
                       alo[mb][0], alo[mb][1], alo[mb][2], alo[mb][3]);
            }
            #pragma unroll
            for (int ng = 0; ng < 4; ng++) {
                uint32_t rowoff = (uint32_t)((b_nrow + ng * 16) * 128);
                uint32_t dyn = (kof + b_khalf) ^ swx;
                uint32_t bh0, bh1, bh2, bh3, bl0, bl1, bl2, bl3;
                ldm_x4(cur + OFF_BHI + rowoff + dyn, bh0, bh1, bh2, bh3);
                ldm_x4(cur + OFF_BLO + rowoff + dyn, bl0, bl1, bl2, bl3);
                #pragma unroll
                for (int mb = 0; mb < 4; mb++) {
                    mma16816(acc[mb][2 * ng + 0], ahi[mb], bh0, bh1);
                    mma16816(acc[mb][2 * ng + 1], ahi[mb], bh2, bh3);
                    mma16816(acc[mb][2 * ng + 0], ahi[mb], bl0, bl1);
                    mma16816(acc[mb][2 * ng + 1], ahi[mb], bl2, bl3);
                    mma16816(acc[mb][2 * ng + 0], alo[mb], bh0, bh1);
                    mma16816(acc[mb][2 * ng + 1], alo[mb], bh2, bh3);
                }
            }
        }
    }

    // ---- epilogue: bias + relu, float2 stores
    const float* sb = (const float*)(sm + SM_BIAS);
    const int mbase = bx * BM + wm * 64 + (lane >> 2);
    const int nbase = wn * 64 + (lane & 3) * 2;

    #pragma unroll
    for (int mb = 0; mb < 4; mb++) {
        #pragma unroll
        for (int nb = 0; nb < 8; nb++) {
            const int n = nbase + nb * 8;
            const float b0 = sb[n], b1 = sb[n + 1];
            const int m0 = mbase + mb * 16;
            float2 v0, v1;
            v0.x = fmaxf(acc[mb][nb][0] + b0, 0.0f);
            v0.y = fmaxf(acc[mb][nb][1] + b1, 0.0f);
            v1.x = fmaxf(acc[mb][nb][2] + b0, 0.0f);
            v1.y = fmaxf(acc[mb][nb][3] + b1, 0.0f);
            *(float2*)(out + (size_t)m0 * NDIM + n) = v0;
            *(float2*)(out + (size_t)(m0 + 8) * NDIM + n) = v1;
        }
    }
}

extern "C" void kernel_launch(void* const* d_in, const int* in_sizes, int n_in,
                              void* d_out, int out_size) {
    const float* X    = (const float*)d_in[0];   // [131072, 256]
    const float* W    = (const float*)d_in[1];   // [256, 256]
    const float* bias = (const float*)d_in[2];   // [256]
    float* out = (float*)d_out;

    cudaFuncSetAttribute(gemm_hmma_kernel,
                         cudaFuncAttributeMaxDynamicSharedMemorySize, SMEM_TOTAL);

    split_w_kernel<<<(NDIM * KDIM) / 256, 256>>>(W);

    const int Brows = in_sizes[0] / KDIM;
    gemm_hmma_kernel<<<Brows / BM, 256, SMEM_TOTAL>>>(X, bias, out);
}

// round 4
// speedup vs baseline: 2.7376x; 1.2023x over previous
#include <cuda_runtime.h>
#include <cuda_bf16.h>
#include <cstdint>

// relu(X[131072,256] @ W[256,256]^T + b), fp32.
// mma.sync m16n8k16 bf16, 3-MMA hi/lo split. R3: RAW-distance-8 MMA ordering,
// A-frag double buffering, reduced live registers.

#define KDIM 256
#define NDIM 256
#define BM   128
#define BN   256
#define KC   64
#define NCHUNK (KDIM / KC)

#define SM_BIAS  0
#define SM_XSTG  1024
#define SM_BUF   33792
#define OFF_AHI  0
#define OFF_ALO  16384
#define OFF_BHI  32768
#define OFF_BLO  65536
#define BUF_BYTES 98304
#define SMEM_TOTAL (SM_BUF + 2 * BUF_BYTES)

__device__ __forceinline__ uint32_t smem_u32(const void* p) {
    uint32_t a;
    asm("{ .reg .u64 t; cvta.to.shared.u64 t, %1; cvt.u32.u64 %0, t; }" : "=r"(a) : "l"(p));
    return a;
}

__device__ __forceinline__ void cp_async16(uint32_t dst, const void* src) {
    asm volatile("cp.async.cg.shared.global [%0], [%1], 16;" :: "r"(dst), "l"(src) : "memory");
}
__device__ __forceinline__ void cp_commit() {
    asm volatile("cp.async.commit_group;" ::: "memory");
}
__device__ __forceinline__ void cp_wait0() {
    asm volatile("cp.async.wait_group 0;" ::: "memory");
}

__device__ __forceinline__ void ldm_x4(uint32_t addr, uint32_t& r0, uint32_t& r1,
                                       uint32_t& r2, uint32_t& r3) {
    asm volatile("ldmatrix.sync.aligned.m8n8.x4.shared.b16 {%0,%1,%2,%3}, [%4];"
                 : "=r"(r0), "=r"(r1), "=r"(r2), "=r"(r3) : "r"(addr));
}

__device__ __forceinline__ void mma16816(float* c, const uint32_t* a, uint32_t b0, uint32_t b1) {
    asm volatile(
        "mma.sync.aligned.m16n8k16.row.col.f32.bf16.bf16.f32 "
        "{%0,%1,%2,%3}, {%4,%5,%6,%7}, {%8,%9}, {%0,%1,%2,%3};"
        : "+f"(c[0]), "+f"(c[1]), "+f"(c[2]), "+f"(c[3])
        : "r"(a[0]), "r"(a[1]), "r"(a[2]), "r"(a[3]), "r"(b0), "r"(b1));
}

__device__ __nv_bfloat16 g_Whi[NDIM * KDIM];
__device__ __nv_bfloat16 g_Wlo[NDIM * KDIM];

__global__ void split_w_kernel(const float* __restrict__ W) {
    int i = blockIdx.x * 256 + threadIdx.x;
    float v = W[i];
    __nv_bfloat16 h = __float2bfloat16(v);
    g_Whi[i] = h;
    g_Wlo[i] = __float2bfloat16(v - __bfloat162float(h));
}

__global__ __launch_bounds__(256, 1)
void gemm_hmma_kernel(const float* __restrict__ X,
                      const float* __restrict__ bias,
                      float* __restrict__ out) {
    extern __shared__ char sm[];
    const uint32_t smb = smem_u32(sm);
    const int tid  = threadIdx.x;
    const int wid  = tid >> 5;
    const int lane = tid & 31;
    const int bx   = blockIdx.x;

    const int wm = wid & 1;        // M half (64 rows)
    const int wn = wid >> 1;       // N quarter (64 cols)

    ((float*)(sm + SM_BIAS))[tid] = bias[tid];

    const float* Xblk = X + (size_t)bx * BM * KDIM;

    const uint32_t swx     = (uint32_t)(lane & 7) << 4;
    const int a_mrow       = wm * 64 + (lane & 7) + ((lane >> 3) & 1) * 8;
    const uint32_t a_khalf = (uint32_t)(lane >> 4) * 16;
    const int b_nrow       = wn * 64 + (lane & 7) + ((lane >> 4) ? 8 : 0);
    const uint32_t b_khalf = (uint32_t)((lane >> 3) & 1) * 16;

    float acc[4][8][4];
    #pragma unroll
    for (int i = 0; i < 4; i++)
        #pragma unroll
        for (int j = 0; j < 8; j++)
            #pragma unroll
            for (int q = 0; q < 4; q++) acc[i][j][q] = 0.0f;

    // ---- prologue: prefetch chunk 0
    {
        #pragma unroll
        for (int it = 0; it < 8; it++) {
            int id = tid + it * 256;
            int r = id >> 4, c = id & 15;
            cp_async16(smb + SM_XSTG + (uint32_t)(r * 256 + c * 16),
                       Xblk + (size_t)r * KDIM + c * 4);
        }
        #pragma unroll
        for (int it = 0; it < 8; it++) {
            int id = tid + it * 256;
            int r = id >> 3, c = id & 7;
            uint32_t off = (uint32_t)(r * 128 + c * 16);
            uint32_t swo = off ^ ((off >> 3) & 0x70);
            cp_async16(smb + SM_BUF + OFF_BHI + swo, g_Whi + r * KDIM + c * 8);
            cp_async16(smb + SM_BUF + OFF_BLO + swo, g_Wlo + r * KDIM + c * 8);
        }
        cp_commit();
    }

    for (int kc = 0; kc < NCHUNK; kc++) {
        const uint32_t cur = smb + SM_BUF + (uint32_t)(kc & 1) * BUF_BYTES;
        const uint32_t nxt = smb + SM_BUF + (uint32_t)((kc & 1) ^ 1) * BUF_BYTES;

        cp_wait0();
        __syncthreads();

        // ---- convert staged fp32 X -> bf16 hi/lo (swizzled)
        #pragma unroll
        for (int it = 0; it < 8; it++) {
            int id = tid + it * 256;
            int r = id >> 4, c = id & 15;
            float4 v = *(const float4*)(sm + SM_XSTG + (uint32_t)(r * 256 + c * 16));
            __nv_bfloat16 h0 = __float2bfloat16(v.x);
            __nv_bfloat16 h1 = __float2bfloat16(v.y);
            __nv_bfloat16 h2 = __float2bfloat16(v.z);
            __nv_bfloat16 h3 = __float2bfloat16(v.w);
            __nv_bfloat16 l0 = __float2bfloat16(v.x - __bfloat162float(h0));
            __nv_bfloat16 l1 = __float2bfloat16(v.y - __bfloat162float(h1));
            __nv_bfloat16 l2 = __float2bfloat16(v.z - __bfloat162float(h2));
            __nv_bfloat16 l3 = __float2bfloat16(v.w - __bfloat162float(h3));
            uint2 hv, lv;
            hv.x = (uint32_t)__bfloat16_as_ushort(h0) | ((uint32_t)__bfloat16_as_ushort(h1) << 16);
            hv.y = (uint32_t)__bfloat16_as_ushort(h2) | ((uint32_t)__bfloat16_as_ushort(h3) << 16);
            lv.x = (uint32_t)__bfloat16_as_ushort(l0) | ((uint32_t)__bfloat16_as_ushort(l1) << 16);
            lv.y = (uint32_t)__bfloat16_as_ushort(l2) | ((uint32_t)__bfloat16_as_ushort(l3) << 16);
            uint32_t off = (uint32_t)(r * 128 + c * 8);
            uint32_t swo = off ^ ((off >> 3) & 0x70);
            *(uint2*)(sm + (cur - smb) + OFF_AHI + swo) = hv;
            *(uint2*)(sm + (cur - smb) + OFF_ALO + swo) = lv;
        }
        __syncthreads();

        // ---- prefetch chunk kc+1 (overlaps MMA below)
        if (kc + 1 < NCHUNK) {
            const int k0 = (kc + 1) * KC;
            #pragma unroll
            for (int it = 0; it < 8; it++) {
                int id = tid + it * 256;
                int r = id >> 4, c = id & 15;
                cp_async16(smb + SM_XSTG + (uint32_t)(r * 256 + c * 16),
                           Xblk + (size_t)r * KDIM + k0 + c * 4);
            }
            #pragma unroll
            for (int it = 0; it < 8; it++) {
                int id = tid + it * 256;
                int r = id >> 3, c = id & 7;
                uint32_t off = (uint32_t)(r * 128 + c * 16);
                uint32_t swo = off ^ ((off >> 3) & 0x70);
                cp_async16(nxt + OFF_BHI + swo, g_Whi + r * KDIM + k0 + c * 8);
                cp_async16(nxt + OFF_BLO + swo, g_Wlo + r * KDIM + k0 + c * 8);
            }
            cp_commit();
        }

        // ---- MMA: per kk, load B frags once, stream mb with A double-buffer,
        //      3 passes per mb (hi.hi / hi.lo / lo.hi) => acc reuse distance 8.
        #pragma unroll
        for (int kk = 0; kk < 4; kk++) {
            const uint32_t kof  = (uint32_t)(kk * 32);
            const uint32_t dynA = (kof + a_khalf) ^ swx;
            const uint32_t dynB = (kof + b_khalf) ^ swx;
            const uint32_t aHiB = cur + OFF_AHI + (uint32_t)(a_mrow * 128) + dynA;
            const uint32_t aLoB = cur + OFF_ALO + (uint32_t)(a_mrow * 128) + dynA;
            const uint32_t bHiB = cur + OFF_BHI + (uint32_t)(b_nrow * 128) + dynB;
            const uint32_t bLoB = cur + OFF_BLO + (uint32_t)(b_nrow * 128) + dynB;

            uint32_t ahi[2][4], alo[2][4];
            ldm_x4(aHiB, ahi[0][0], ahi[0][1], ahi[0][2], ahi[0][3]);
            ldm_x4(aLoB, alo[0][0], alo[0][1], alo[0][2], alo[0][3]);

            uint32_t bh[4][4], bl[4][4];
            #pragma unroll
            for (int ng = 0; ng < 4; ng++) {
                ldm_x4(bHiB + (uint32_t)(ng * 2048), bh[ng][0], bh[ng][1], bh[ng][2], bh[ng][3]);
                ldm_x4(bLoB + (uint32_t)(ng * 2048), bl[ng][0], bl[ng][1], bl[ng][2], bl[ng][3]);
            }

            #pragma unroll
            for (int mb = 0; mb < 4; mb++) {
                const int cb = mb & 1;
                if (mb < 3) {
                    const int nb = cb ^ 1;
                    ldm_x4(aHiB + (uint32_t)((mb + 1) * 2048),
                           ahi[nb][0], ahi[nb][1], ahi[nb][2], ahi[nb][3]);
                    ldm_x4(aLoB + (uint32_t)((mb + 1) * 2048),
                           alo[nb][0], alo[nb][1], alo[nb][2], alo[nb][3]);
                }
                #pragma unroll
                for (int ng = 0; ng < 4; ng++) {
                    mma16816(acc[mb][2 * ng + 0], ahi[cb], bh[ng][0], bh[ng][1]);
                    mma16816(acc[mb][2 * ng + 1], ahi[cb], bh[ng][2], bh[ng][3]);
                }
                #pragma unroll
                for (int ng = 0; ng < 4; ng++) {
                    mma16816(acc[mb][2 * ng + 0], ahi[cb], bl[ng][0], bl[ng][1]);
                    mma16816(acc[mb][2 * ng + 1], ahi[cb], bl[ng][2], bl[ng][3]);
                }
                #pragma unroll
                for (int ng = 0; ng < 4; ng++) {
                    mma16816(acc[mb][2 * ng + 0], alo[cb], bh[ng][0], bh[ng][1]);
                    mma16816(acc[mb][2 * ng + 1], alo[cb], bh[ng][2], bh[ng][3]);
                }
            }
        }
    }

    // ---- epilogue: bias + relu
    const float* sb = (const float*)(sm + SM_BIAS);
    const int mbase = bx * BM + wm * 64 + (lane >> 2);
    const int nbase = wn * 64 + (lane & 3) * 2;

    #pragma unroll
    for (int mb = 0; mb < 4; mb++) {
        #pragma unroll
        for (int nb = 0; nb < 8; nb++) {
            const int n = nbase + nb * 8;
            const float b0 = sb[n], b1 = sb[n + 1];
            const int m0 = mbase + mb * 16;
            float2 v0, v1;
            v0.x = fmaxf(acc[mb][nb][0] + b0, 0.0f);
            v0.y = fmaxf(acc[mb][nb][1] + b1, 0.0f);
            v1.x = fmaxf(acc[mb][nb][2] + b0, 0.0f);
            v1.y = fmaxf(acc[mb][nb][3] + b1, 0.0f);
            *(float2*)(out + (size_t)m0 * NDIM + n) = v0;
            *(float2*)(out + (size_t)(m0 + 8) * NDIM + n) = v1;
        }
    }
}

extern "C" void kernel_launch(void* const* d_in, const int* in_sizes, int n_in,
                              void* d_out, int out_size) {
    const float* X    = (const float*)d_in[0];
    const float* W    = (const float*)d_in[1];
    const float* bias = (const float*)d_in[2];
    float* out = (float*)d_out;

    cudaFuncSetAttribute(gemm_hmma_kernel,
                         cudaFuncAttributeMaxDynamicSharedMemorySize, SMEM_TOTAL);

    split_w_kernel<<<(NDIM * KDIM) / 256, 256>>>(W);

    const int Brows = in_sizes[0] / KDIM;
    gemm_hmma_kernel<<<Brows / BM, 256, SMEM_TOTAL>>>(X, bias, out);
}

// round 5
// speedup vs baseline: 2.8066x; 1.0252x over previous
#include <cuda_runtime.h>
#include <cuda_bf16.h>
#include <cstdint>

// relu(X[131072,256] @ W[256,256]^T + b), fp32.
// mma.sync m16n8k16 bf16, 3-MMA hi/lo split.
// R4: 512 threads (16 warps, 4/SMSP), warp tile 32x64, acc=64 regs/thread.

#define KDIM 256
#define NDIM 256
#define BM   128
#define KC   64
#define NCHUNK (KDIM / KC)
#define NTHR 512

#define SM_BIAS  0
#define SM_XSTG  1024
#define SM_BUF   33792
#define OFF_AHI  0
#define OFF_ALO  16384
#define OFF_BHI  32768
#define OFF_BLO  65536
#define BUF_BYTES 98304
#define SMEM_TOTAL (SM_BUF + 2 * BUF_BYTES)

__device__ __forceinline__ uint32_t smem_u32(const void* p) {
    uint32_t a;
    asm("{ .reg .u64 t; cvta.to.shared.u64 t, %1; cvt.u32.u64 %0, t; }" : "=r"(a) : "l"(p));
    return a;
}

__device__ __forceinline__ void cp_async16(uint32_t dst, const void* src) {
    asm volatile("cp.async.cg.shared.global [%0], [%1], 16;" :: "r"(dst), "l"(src) : "memory");
}
__device__ __forceinline__ void cp_commit() {
    asm volatile("cp.async.commit_group;" ::: "memory");
}
__device__ __forceinline__ void cp_wait0() {
    asm volatile("cp.async.wait_group 0;" ::: "memory");
}

__device__ __forceinline__ void ldm_x4(uint32_t addr, uint32_t& r0, uint32_t& r1,
                                       uint32_t& r2, uint32_t& r3) {
    asm volatile("ldmatrix.sync.aligned.m8n8.x4.shared.b16 {%0,%1,%2,%3}, [%4];"
                 : "=r"(r0), "=r"(r1), "=r"(r2), "=r"(r3) : "r"(addr));
}

__device__ __forceinline__ void mma16816(float* c, const uint32_t* a, uint32_t b0, uint32_t b1) {
    asm volatile(
        "mma.sync.aligned.m16n8k16.row.col.f32.bf16.bf16.f32 "
        "{%0,%1,%2,%3}, {%4,%5,%6,%7}, {%8,%9}, {%0,%1,%2,%3};"
        : "+f"(c[0]), "+f"(c[1]), "+f"(c[2]), "+f"(c[3])
        : "r"(a[0]), "r"(a[1]), "r"(a[2]), "r"(a[3]), "r"(b0), "r"(b1));
}

__device__ __nv_bfloat16 g_Whi[NDIM * KDIM];
__device__ __nv_bfloat16 g_Wlo[NDIM * KDIM];

__global__ void split_w_kernel(const float* __restrict__ W) {
    int i = blockIdx.x * 256 + threadIdx.x;
    float v = W[i];
    __nv_bfloat16 h = __float2bfloat16(v);
    g_Whi[i] = h;
    g_Wlo[i] = __float2bfloat16(v - __bfloat162float(h));
}

__global__ __launch_bounds__(NTHR, 1)
void gemm_hmma_kernel(const float* __restrict__ X,
                      const float* __restrict__ bias,
                      float* __restrict__ out) {
    extern __shared__ char sm[];
    const uint32_t smb = smem_u32(sm);
    const int tid  = threadIdx.x;
    const int wid  = tid >> 5;
    const int lane = tid & 31;
    const int bx   = blockIdx.x;

    const int wm = wid & 3;        // M quarter (32 rows)
    const int wn = wid >> 2;       // N quarter (64 cols)

    if (tid < 256) ((float*)(sm + SM_BIAS))[tid] = bias[tid];

    const float* Xblk = X + (size_t)bx * BM * KDIM;

    const uint32_t swx     = (uint32_t)(lane & 7) << 4;
    const int a_mrow       = wm * 32 + (lane & 7) + ((lane >> 3) & 1) * 8;
    const uint32_t a_khalf = (uint32_t)(lane >> 4) * 16;
    const int b_nrow       = wn * 64 + (lane & 7) + ((lane >> 4) ? 8 : 0);
    const uint32_t b_khalf = (uint32_t)((lane >> 3) & 1) * 16;

    float acc[2][8][4];
    #pragma unroll
    for (int i = 0; i < 2; i++)
        #pragma unroll
        for (int j = 0; j < 8; j++)
            #pragma unroll
            for (int q = 0; q < 4; q++) acc[i][j][q] = 0.0f;

    // ---- prologue: prefetch chunk 0
    {
        #pragma unroll
        for (int it = 0; it < 4; it++) {
            int id = tid + it * NTHR;
            int r = id >> 4, c = id & 15;
            cp_async16(smb + SM_XSTG + (uint32_t)(r * 256 + c * 16),
                       Xblk + (size_t)r * KDIM + c * 4);
        }
        #pragma unroll
        for (int it = 0; it < 4; it++) {
            int id = tid + it * NTHR;
            int r = id >> 3, c = id & 7;
            uint32_t off = (uint32_t)(r * 128 + c * 16);
            uint32_t swo = off ^ ((off >> 3) & 0x70);
            cp_async16(smb + SM_BUF + OFF_BHI + swo, g_Whi + r * KDIM + c * 8);
            cp_async16(smb + SM_BUF + OFF_BLO + swo, g_Wlo + r * KDIM + c * 8);
        }
        cp_commit();
    }

    for (int kc = 0; kc < NCHUNK; kc++) {
        const uint32_t cur = smb + SM_BUF + (uint32_t)(kc & 1) * BUF_BYTES;
        const uint32_t nxt = smb + SM_BUF + (uint32_t)((kc & 1) ^ 1) * BUF_BYTES;

        cp_wait0();
        __syncthreads();

        // ---- convert staged fp32 X -> bf16 hi/lo (swizzled)
        #pragma unroll
        for (int it = 0; it < 4; it++) {
            int id = tid + it * NTHR;
            int r = id >> 4, c = id & 15;
            float4 v = *(const float4*)(sm + SM_XSTG + (uint32_t)(r * 256 + c * 16));
            __nv_bfloat16 h0 = __float2bfloat16(v.x);
            __nv_bfloat16 h1 = __float2bfloat16(v.y);
            __nv_bfloat16 h2 = __float2bfloat16(v.z);
            __nv_bfloat16 h3 = __float2bfloat16(v.w);
            __nv_bfloat16 l0 = __float2bfloat16(v.x - __bfloat162float(h0));
            __nv_bfloat16 l1 = __float2bfloat16(v.y - __bfloat162float(h1));
            __nv_bfloat16 l2 = __float2bfloat16(v.z - __bfloat162float(h2));
            __nv_bfloat16 l3 = __float2bfloat16(v.w - __bfloat162float(h3));
            uint2 hv, lv;
            hv.x = (uint32_t)__bfloat16_as_ushort(h0) | ((uint32_t)__bfloat16_as_ushort(h1) << 16);
            hv.y = (uint32_t)__bfloat16_as_ushort(h2) | ((uint32_t)__bfloat16_as_ushort(h3) << 16);
            lv.x = (uint32_t)__bfloat16_as_ushort(l0) | ((uint32_t)__bfloat16_as_ushort(l1) << 16);
            lv.y = (uint32_t)__bfloat16_as_ushort(l2) | ((uint32_t)__bfloat16_as_ushort(l3) << 16);
            uint32_t off = (uint32_t)(r * 128 + c * 8);
            uint32_t swo = off ^ ((off >> 3) & 0x70);
            *(uint2*)(sm + (cur - smb) + OFF_AHI + swo) = hv;
            *(uint2*)(sm + (cur - smb) + OFF_ALO + swo) = lv;
        }
        __syncthreads();

        // ---- prefetch chunk kc+1 (overlaps MMA below)
        if (kc + 1 < NCHUNK) {
            const int k0 = (kc + 1) * KC;
            #pragma unroll
            for (int it = 0; it < 4; it++) {
                int id = tid + it * NTHR;
                int r = id >> 4, c = id & 15;
                cp_async16(smb + SM_XSTG + (uint32_t)(r * 256 + c * 16),
                           Xblk + (size_t)r * KDIM + k0 + c * 4);
            }
            #pragma unroll
            for (int it = 0; it < 4; it++) {
                int id = tid + it * NTHR;
                int r = id >> 3, c = id & 7;
                uint32_t off = (uint32_t)(r * 128 + c * 16);
                uint32_t swo = off ^ ((off >> 3) & 0x70);
                cp_async16(nxt + OFF_BHI + swo, g_Whi + r * KDIM + k0 + c * 8);
                cp_async16(nxt + OFF_BLO + swo, g_Wlo + r * KDIM + k0 + c * 8);
            }
            cp_commit();
        }

        // ---- MMA: per kk, A frags once (2 mb), B frags double-buffered over ng
        #pragma unroll
        for (int kk = 0; kk < 4; kk++) {
            const uint32_t kof  = (uint32_t)(kk * 32);
            const uint32_t dynA = (kof + a_khalf) ^ swx;
            const uint32_t dynB = (kof + b_khalf) ^ swx;
            const uint32_t aHiB = cur + OFF_AHI + (uint32_t)(a_mrow * 128) + dynA;
            const uint32_t aLoB = cur + OFF_ALO + (uint32_t)(a_mrow * 128) + dynA;
            const uint32_t bHiB = cur + OFF_BHI + (uint32_t)(b_nrow * 128) + dynB;
            const uint32_t bLoB = cur + OFF_BLO + (uint32_t)(b_nrow * 128) + dynB;

            uint32_t ahi[2][4], alo[2][4];
            ldm_x4(aHiB,        ahi[0][0], ahi[0][1], ahi[0][2], ahi[0][3]);
            ldm_x4(aHiB + 2048, ahi[1][0], ahi[1][1], ahi[1][2], ahi[1][3]);
            ldm_x4(aLoB,        alo[0][0], alo[0][1], alo[0][2], alo[0][3]);
            ldm_x4(aLoB + 2048, alo[1][0], alo[1][1], alo[1][2], alo[1][3]);

            uint32_t bh[2][4], bl[2][4];
            ldm_x4(bHiB, bh[0][0], bh[0][1], bh[0][2], bh[0][3]);
            ldm_x4(bLoB, bl[0][0], bl[0][1], bl[0][2], bl[0][3]);

            #pragma unroll
            for (int ng = 0; ng < 4; ng++) {
                const int cb = ng & 1;
                if (ng < 3) {
                    const int nb = cb ^ 1;
                    ldm_x4(bHiB + (uint32_t)((ng + 1) * 2048),
                           bh[nb][0], bh[nb][1], bh[nb][2], bh[nb][3]);
                    ldm_x4(bLoB + (uint32_t)((ng + 1) * 2048),
                           bl[nb][0], bl[nb][1], bl[nb][2], bl[nb][3]);
                }
                // pass 1: hi*hi
                mma16816(acc[0][2 * ng + 0], ahi[0], bh[cb][0], bh[cb][1]);
                mma16816(acc[0][2 * ng + 1], ahi[0], bh[cb][2], bh[cb][3]);
                mma16816(acc[1][2 * ng + 0], ahi[1], bh[cb][0], bh[cb][1]);
                mma16816(acc[1][2 * ng + 1], ahi[1], bh[cb][2], bh[cb][3]);
                // pass 2: hi*lo
                mma16816(acc[0][2 * ng + 0], ahi[0], bl[cb][0], bl[cb][1]);
                mma16816(acc[0][2 * ng + 1], ahi[0], bl[cb][2], bl[cb][3]);
                mma16816(acc[1][2 * ng + 0], ahi[1], bl[cb][0], bl[cb][1]);
                mma16816(acc[1][2 * ng + 1], ahi[1], bl[cb][2], bl[cb][3]);
                // pass 3: lo*hi
                mma16816(acc[0][2 * ng + 0], alo[0], bh[cb][0], bh[cb][1]);
                mma16816(acc[0][2 * ng + 1], alo[0], bh[cb][2], bh[cb][3]);
                mma16816(acc[1][2 * ng + 0], alo[1], bh[cb][0], bh[cb][1]);
                mma16816(acc[1][2 * ng + 1], alo[1], bh[cb][2], bh[cb][3]);
            }
        }
    }

    // ---- epilogue: bias + relu
    const float* sb = (const float*)(sm + SM_BIAS);
    const int mbase = bx * BM + wm * 32 + (lane >> 2);
    const int nbase = wn * 64 + (lane & 3) * 2;

    #pragma unroll
    for (int mb = 0; mb < 2; mb++) {
        #pragma unroll
        for (int nb = 0; nb < 8; nb++) {
            const int n = nbase + nb * 8;
            const float b0 = sb[n], b1 = sb[n + 1];
            const int m0 = mbase + mb * 16;
            float2 v0, v1;
            v0.x = fmaxf(acc[mb][nb][0] + b0, 0.0f);
            v0.y = fmaxf(acc[mb][nb][1] + b1, 0.0f);
            v1.x = fmaxf(acc[mb][nb][2] + b0, 0.0f);
            v1.y = fmaxf(acc[mb][nb][3] + b1, 0.0f);
            *(float2*)(out + (size_t)m0 * NDIM + n) = v0;
            *(float2*)(out + (size_t)(m0 + 8) * NDIM + n) = v1;
        }
    }
}

extern "C" void kernel_launch(void* const* d_in, const int* in_sizes, int n_in,
                              void* d_out, int out_size) {
    const float* X    = (const float*)d_in[0];
    const float* W    = (const float*)d_in[1];
    const float* bias = (const float*)d_in[2];
    float* out = (float*)d_out;

    cudaFuncSetAttribute(gemm_hmma_kernel,
                         cudaFuncAttributeMaxDynamicSharedMemorySize, SMEM_TOTAL);

    split_w_kernel<<<(NDIM * KDIM) / 256, 256>>>(W);

    const int Brows = in_sizes[0] / KDIM;
    gemm_hmma_kernel<<<Brows / BM, NTHR, SMEM_TOTAL>>>(X, bias, out);
}

// round 6
// speedup vs baseline: 2.8679x; 1.0218x over previous
#include <cuda_runtime.h>
#include <cuda_bf16.h>
#include <cstdint>

// relu(X[131072,256] @ W[256,256]^T + b), fp32.
// mma.sync m16n8k16 bf16, 3-MMA hi/lo split.
// R5: convert bubble eliminated — X(kc+1) LDG->cvt->STS interleaved into the
// MMA loop of chunk kc; one __syncthreads per chunk; no fp32 staging buffer.

#define KDIM 256
#define NDIM 256
#define BM   128
#define KC   64
#define NCHUNK (KDIM / KC)
#define NTHR 512

#define SM_BIAS  0
#define SM_BUF   1024
#define OFF_AHI  0
#define OFF_ALO  16384
#define OFF_BHI  32768
#define OFF_BLO  65536
#define BUF_BYTES 98304
#define SMEM_TOTAL (SM_BUF + 2 * BUF_BYTES)   // 197632

__device__ __forceinline__ uint32_t smem_u32(const void* p) {
    uint32_t a;
    asm("{ .reg .u64 t; cvta.to.shared.u64 t, %1; cvt.u32.u64 %0, t; }" : "=r"(a) : "l"(p));
    return a;
}

__device__ __forceinline__ void cp_async16(uint32_t dst, const void* src) {
    asm volatile("cp.async.cg.shared.global [%0], [%1], 16;" :: "r"(dst), "l"(src) : "memory");
}
__device__ __forceinline__ void cp_commit() {
    asm volatile("cp.async.commit_group;" ::: "memory");
}
__device__ __forceinline__ void cp_wait0() {
    asm volatile("cp.async.wait_group 0;" ::: "memory");
}

__device__ __forceinline__ void ldm_x4(uint32_t addr, uint32_t& r0, uint32_t& r1,
                                       uint32_t& r2, uint32_t& r3) {
    asm volatile("ldmatrix.sync.aligned.m8n8.x4.shared.b16 {%0,%1,%2,%3}, [%4];"
                 : "=r"(r0), "=r"(r1), "=r"(r2), "=r"(r3) : "r"(addr));
}

__device__ __forceinline__ void mma16816(float* c, const uint32_t* a, uint32_t b0, uint32_t b1) {
    asm volatile(
        "mma.sync.aligned.m16n8k16.row.col.f32.bf16.bf16.f32 "
        "{%0,%1,%2,%3}, {%4,%5,%6,%7}, {%8,%9}, {%0,%1,%2,%3};"
        : "+f"(c[0]), "+f"(c[1]), "+f"(c[2]), "+f"(c[3])
        : "r"(a[0]), "r"(a[1]), "r"(a[2]), "r"(a[3]), "r"(b0), "r"(b1));
}

__device__ __nv_bfloat16 g_Whi[NDIM * KDIM];
__device__ __nv_bfloat16 g_Wlo[NDIM * KDIM];

__global__ void split_w_kernel(const float* __restrict__ W) {
    int i = blockIdx.x * 256 + threadIdx.x;
    float v = W[i];
    __nv_bfloat16 h = __float2bfloat16(v);
    g_Whi[i] = h;
    g_Wlo[i] = __float2bfloat16(v - __bfloat162float(h));
}

// convert one float4 (4 K values) -> bf16 hi/lo and store swizzled
__device__ __forceinline__ void conv_store(float4 v, char* ahi, char* alo,
                                           int row, int c) {
    __nv_bfloat16 h0 = __float2bfloat16(v.x);
    __nv_bfloat16 h1 = __float2bfloat16(v.y);
    __nv_bfloat16 h2 = __float2bfloat16(v.z);
    __nv_bfloat16 h3 = __float2bfloat16(v.w);
    __nv_bfloat16 l0 = __float2bfloat16(v.x - __bfloat162float(h0));
    __nv_bfloat16 l1 = __float2bfloat16(v.y - __bfloat162float(h1));
    __nv_bfloat16 l2 = __float2bfloat16(v.z - __bfloat162float(h2));
    __nv_bfloat16 l3 = __float2bfloat16(v.w - __bfloat162float(h3));
    uint2 hv, lv;
    hv.x = (uint32_t)__bfloat16_as_ushort(h0) | ((uint32_t)__bfloat16_as_ushort(h1) << 16);
    hv.y = (uint32_t)__bfloat16_as_ushort(h2) | ((uint32_t)__bfloat16_as_ushort(h3) << 16);
    lv.x = (uint32_t)__bfloat16_as_ushort(l0) | ((uint32_t)__bfloat16_as_ushort(l1) << 16);
    lv.y = (uint32_t)__bfloat16_as_ushort(l2) | ((uint32_t)__bfloat16_as_ushort(l3) << 16);
    uint32_t off = (uint32_t)(row * 128 + c * 8);
    uint32_t swo = off ^ ((off >> 3) & 0x70);
    *(uint2*)(ahi + swo) = hv;
    *(uint2*)(alo + swo) = lv;
}

__global__ __launch_bounds__(NTHR, 1)
void gemm_hmma_kernel(const float* __restrict__ X,
                      const float* __restrict__ bias,
                      float* __restrict__ out) {
    extern __shared__ char sm[];
    const uint32_t smb = smem_u32(sm);
    const int tid  = threadIdx.x;
    const int wid  = tid >> 5;
    const int lane = tid & 31;
    const int bx   = blockIdx.x;

    const int wm = wid & 3;        // M quarter (32 rows)
    const int wn = wid >> 2;       // N quarter (64 cols)

    if (tid < 256) ((float*)(sm + SM_BIAS))[tid] = bias[tid];

    const float* Xblk = X + (size_t)bx * BM * KDIM;

    const uint32_t swx     = (uint32_t)(lane & 7) << 4;
    const int a_mrow       = wm * 32 + (lane & 7) + ((lane >> 3) & 1) * 8;
    const uint32_t a_khalf = (uint32_t)(lane >> 4) * 16;
    const int b_nrow       = wn * 64 + (lane & 7) + ((lane >> 4) ? 8 : 0);
    const uint32_t b_khalf = (uint32_t)((lane >> 3) & 1) * 16;

    // per-thread X/A coordinates (rows xr+32*it, float4 slot xc)
    const int xr = tid >> 4;
    const int xc = tid & 15;

    float acc[2][8][4];
    #pragma unroll
    for (int i = 0; i < 2; i++)
        #pragma unroll
        for (int j = 0; j < 8; j++)
            #pragma unroll
            for (int q = 0; q < 4; q++) acc[i][j][q] = 0.0f;

    // ---- prologue: build chunk 0 directly (LDG->cvt->STS A, cp.async B)
    {
        char* ahi = sm + SM_BUF + OFF_AHI;
        char* alo = sm + SM_BUF + OFF_ALO;
        #pragma unroll
        for (int it = 0; it < 4; it++) {
            float4 v = *(const float4*)(Xblk + (size_t)(xr + it * 32) * KDIM + xc * 4);
            conv_store(v, ahi, alo, xr + it * 32, xc);
        }
        #pragma unroll
        for (int it = 0; it < 8; it++) {
            int id = tid + (it & 3) * NTHR;
            int r = id >> 3, c = id & 7;
            uint32_t off = (uint32_t)(r * 128 + c * 16);
            uint32_t swo = off ^ ((off >> 3) & 0x70);
            if (it < 4)
                cp_async16(smb + SM_BUF + OFF_BHI + swo, g_Whi + r * KDIM + c * 8);
            else
                cp_async16(smb + SM_BUF + OFF_BLO + swo, g_Wlo + r * KDIM + c * 8);
        }
        cp_commit();
        cp_wait0();
        __syncthreads();
    }

    for (int kc = 0; kc < NCHUNK; kc++) {
        const uint32_t cur  = smb + SM_BUF + (uint32_t)(kc & 1) * BUF_BYTES;
        const uint32_t nxtb = smb + SM_BUF + (uint32_t)((kc & 1) ^ 1) * BUF_BYTES;
        char* nahi = sm + (nxtb - smb) + OFF_AHI;
        char* nalo = sm + (nxtb - smb) + OFF_ALO;
        const bool pre = (kc + 1 < NCHUNK);
        const int k0 = (kc + 1) * KC;

        float4 xv[4];

        #pragma unroll
        for (int kk = 0; kk < 4; kk++) {
            // ---- prefetch work for chunk kc+1, interleaved with MMA
            if (pre && kk == 0) {
                #pragma unroll
                for (int it = 0; it < 4; it++)
                    xv[it] = *(const float4*)(Xblk + (size_t)(xr + it * 32) * KDIM + k0 + xc * 4);
            }
            if (pre) {
                #pragma unroll
                for (int q = 0; q < 2; q++) {
                    const int it = (kk & 1) * 2 + q;
                    const int id = tid + it * NTHR;
                    const int r = id >> 3, c = id & 7;
                    uint32_t off = (uint32_t)(r * 128 + c * 16);
                    uint32_t swo = off ^ ((off >> 3) & 0x70);
                    if (kk < 2)
                        cp_async16(nxtb + OFF_BHI + swo, g_Whi + r * KDIM + k0 + c * 8);
                    else
                        cp_async16(nxtb + OFF_BLO + swo, g_Wlo + r * KDIM + k0 + c * 8);
                }
            }

            // ---- ldmatrix + MMA for kk
            const uint32_t kof  = (uint32_t)(kk * 32);
            const uint32_t dynA = (kof + a_khalf) ^ swx;
            const uint32_t dynB = (kof + b_khalf) ^ swx;
            const uint32_t aHiB = cur + OFF_AHI + (uint32_t)(a_mrow * 128) + dynA;
            const uint32_t aLoB = cur + OFF_ALO + (uint32_t)(a_mrow * 128) + dynA;
            const uint32_t bHiB = cur + OFF_BHI + (uint32_t)(b_nrow * 128) + dynB;
            const uint32_t bLoB = cur + OFF_BLO + (uint32_t)(b_nrow * 128) + dynB;

            uint32_t ahi[2][4], alo[2][4];
            ldm_x4(aHiB,        ahi[0][0], ahi[0][1], ahi[0][2], ahi[0][3]);
            ldm_x4(aHiB + 2048, ahi[1][0], ahi[1][1], ahi[1][2], ahi[1][3]);
            ldm_x4(aLoB,        alo[0][0], alo[0][1], alo[0][2], alo[0][3]);
            ldm_x4(aLoB + 2048, alo[1][0], alo[1][1], alo[1][2], alo[1][3]);

            uint32_t bh[2][4], bl[2][4];
            ldm_x4(bHiB, bh[0][0], bh[0][1], bh[0][2], bh[0][3]);
            ldm_x4(bLoB, bl[0][0], bl[0][1], bl[0][2], bl[0][3]);

            #pragma unroll
            for (int ng = 0; ng < 4; ng++) {
                const int cb = ng & 1;
                if (ng < 3) {
                    const int nb = cb ^ 1;
                    ldm_x4(bHiB + (uint32_t)((ng + 1) * 2048),
                           bh[nb][0], bh[nb][1], bh[nb][2], bh[nb][3]);
                    ldm_x4(bLoB + (uint32_t)((ng + 1) * 2048),
                           bl[nb][0], bl[nb][1], bl[nb][2], bl[nb][3]);
                }
                mma16816(acc[0][2 * ng + 0], ahi[0], bh[cb][0], bh[cb][1]);
                mma16816(acc[0][2 * ng + 1], ahi[0], bh[cb][2], bh[cb][3]);
                mma16816(acc[1][2 * ng + 0], ahi[1], bh[cb][0], bh[cb][1]);
                mma16816(acc[1][2 * ng + 1], ahi[1], bh[cb][2], bh[cb][3]);
                mma16816(acc[0][2 * ng + 0], ahi[0], bl[cb][0], bl[cb][1]);
                mma16816(acc[0][2 * ng + 1], ahi[0], bl[cb][2], bl[cb][3]);
                mma16816(acc[1][2 * ng + 0], ahi[1], bl[cb][0], bl[cb][1]);
                mma16816(acc[1][2 * ng + 1], ahi[1], bl[cb][2], bl[cb][3]);
                mma16816(acc[0][2 * ng + 0], alo[0], bh[cb][0], bh[cb][1]);
                mma16816(acc[0][2 * ng + 1], alo[0], bh[cb][2], bh[cb][3]);
                mma16816(acc[1][2 * ng + 0], alo[1], bh[cb][0], bh[cb][1]);
                mma16816(acc[1][2 * ng + 1], alo[1], bh[cb][2], bh[cb][3]);
            }

            // ---- convert prefetched X into nxt A buffers (off critical path)
            if (pre && kk == 1) {
                conv_store(xv[0], nahi, nalo, xr,      xc);
                conv_store(xv[1], nahi, nalo, xr + 32, xc);
            }
            if (pre && kk == 2) {
                conv_store(xv[2], nahi, nalo, xr + 64, xc);
                conv_store(xv[3], nahi, nalo, xr + 96, xc);
            }
        }

        if (pre) {
            cp_commit();
            cp_wait0();
        }
        __syncthreads();
    }

    // ---- epilogue: bias + relu
    const float* sb = (const float*)(sm + SM_BIAS);
    const int mbase = bx * BM + wm * 32 + (lane >> 2);
    const int nbase = wn * 64 + (lane & 3) * 2;

    #pragma unroll
    for (int mb = 0; mb < 2; mb++) {
        #pragma unroll
        for (int nb = 0; nb < 8; nb++) {
            const int n = nbase + nb * 8;
            const float b0 = sb[n], b1 = sb[n + 1];
            const int m0 = mbase + mb * 16;
            float2 v0, v1;
            v0.x = fmaxf(acc[mb][nb][0] + b0, 0.0f);
            v0.y = fmaxf(acc[mb][nb][1] + b1, 0.0f);
            v1.x = fmaxf(acc[mb][nb][2] + b0, 0.0f);
            v1.y = fmaxf(acc[mb][nb][3] + b1, 0.0f);
            *(float2*)(out + (size_t)m0 * NDIM + n) = v0;
            *(float2*)(out + (size_t)(m0 + 8) * NDIM + n) = v1;
        }
    }
}

extern "C" void kernel_launch(void* const* d_in, const int* in_sizes, int n_in,
                              void* d_out, int out_size) {
    const float* X    = (const float*)d_in[0];
    const float* W    = (const float*)d_in[1];
    const float* bias = (const float*)d_in[2];
    float* out = (float*)d_out;

    cudaFuncSetAttribute(gemm_hmma_kernel,
                         cudaFuncAttributeMaxDynamicSharedMemorySize, SMEM_TOTAL);

    split_w_kernel<<<(NDIM * KDIM) / 256, 256>>>(W);

    const int Brows = in_sizes[0] / KDIM;
    gemm_hmma_kernel<<<Brows / BM, NTHR, SMEM_TOTAL>>>(X, bias, out);
}

// round 7
// speedup vs baseline: 3.6332x; 1.2668x over previous
#include <cuda_runtime.h>
#include <cuda_fp16.h>
#include <cstdint>

// relu(X[131072,256] @ W[256,256]^T + b), fp32.
// R6: fp16 2-term split — X = Xhi+Xlo (fp16), W = fp16(W).
// C = Xhi*Wh + Xlo*Wh; error = X*(W-fp16(W)) ~ 1e-4 norm-relative.
// mma.sync m16n8k16 f16, 8 MMAs per (kk,ng) instead of 12.

#define KDIM 256
#define NDIM 256
#define BM   128
#define KC   64
#define NCHUNK (KDIM / KC)
#define NTHR 512

#define SM_BIAS  0
#define SM_BUF   1024
#define OFF_AHI  0          // 128 rows x 128B = 16KB
#define OFF_ALO  16384
#define OFF_B    32768      // 256 rows x 128B = 32KB
#define BUF_BYTES 65536
#define SMEM_TOTAL (SM_BUF + 2 * BUF_BYTES)   // 132096

__device__ __forceinline__ uint32_t smem_u32(const void* p) {
    uint32_t a;
    asm("{ .reg .u64 t; cvta.to.shared.u64 t, %1; cvt.u32.u64 %0, t; }" : "=r"(a) : "l"(p));
    return a;
}

__device__ __forceinline__ void cp_async16(uint32_t dst, const void* src) {
    asm volatile("cp.async.cg.shared.global [%0], [%1], 16;" :: "r"(dst), "l"(src) : "memory");
}
__device__ __forceinline__ void cp_commit() {
    asm volatile("cp.async.commit_group;" ::: "memory");
}
__device__ __forceinline__ void cp_wait0() {
    asm volatile("cp.async.wait_group 0;" ::: "memory");
}

__device__ __forceinline__ void ldm_x4(uint32_t addr, uint32_t& r0, uint32_t& r1,
                                       uint32_t& r2, uint32_t& r3) {
    asm volatile("ldmatrix.sync.aligned.m8n8.x4.shared.b16 {%0,%1,%2,%3}, [%4];"
                 : "=r"(r0), "=r"(r1), "=r"(r2), "=r"(r3) : "r"(addr));
}

__device__ __forceinline__ void mma16816(float* c, const uint32_t* a, uint32_t b0, uint32_t b1) {
    asm volatile(
        "mma.sync.aligned.m16n8k16.row.col.f32.f16.f16.f32 "
        "{%0,%1,%2,%3}, {%4,%5,%6,%7}, {%8,%9}, {%0,%1,%2,%3};"
        : "+f"(c[0]), "+f"(c[1]), "+f"(c[2]), "+f"(c[3])
        : "r"(a[0]), "r"(a[1]), "r"(a[2]), "r"(a[3]), "r"(b0), "r"(b1));
}

__device__ __half g_Wh[NDIM * KDIM];

__global__ void split_w_kernel(const float* __restrict__ W) {
    int i = blockIdx.x * 256 + threadIdx.x;
    g_Wh[i] = __float2half_rn(W[i]);
}

// convert one float4 (4 K values) -> fp16 hi/lo and store swizzled
__device__ __forceinline__ void conv_store(float4 v, char* ahi, char* alo,
                                           int row, int c) {
    __half h0 = __float2half_rn(v.x);
    __half h1 = __float2half_rn(v.y);
    __half h2 = __float2half_rn(v.z);
    __half h3 = __float2half_rn(v.w);
    __half l0 = __float2half_rn(v.x - __half2float(h0));
    __half l1 = __float2half_rn(v.y - __half2float(h1));
    __half l2 = __float2half_rn(v.z - __half2float(h2));
    __half l3 = __float2half_rn(v.w - __half2float(h3));
    uint2 hv, lv;
    hv.x = (uint32_t)__half_as_ushort(h0) | ((uint32_t)__half_as_ushort(h1) << 16);
    hv.y = (uint32_t)__half_as_ushort(h2) | ((uint32_t)__half_as_ushort(h3) << 16);
    lv.x = (uint32_t)__half_as_ushort(l0) | ((uint32_t)__half_as_ushort(l1) << 16);
    lv.y = (uint32_t)__half_as_ushort(l2) | ((uint32_t)__half_as_ushort(l3) << 16);
    uint32_t off = (uint32_t)(row * 128 + c * 8);
    uint32_t swo = off ^ ((off >> 3) & 0x70);
    *(uint2*)(ahi + swo) = hv;
    *(uint2*)(alo + swo) = lv;
}

__global__ __launch_bounds__(NTHR, 1)
void gemm_hmma_kernel(const float* __restrict__ X,
                      const float* __restrict__ bias,
                      float* __restrict__ out) {
    extern __shared__ char sm[];
    const uint32_t smb = smem_u32(sm);
    const int tid  = threadIdx.x;
    const int wid  = tid >> 5;
    const int lane = tid & 31;
    const int bx   = blockIdx.x;

    const int wm = wid & 3;        // M quarter (32 rows)
    const int wn = wid >> 2;       // N quarter (64 cols)

    if (tid < 256) ((float*)(sm + SM_BIAS))[tid] = bias[tid];

    const float* Xblk = X + (size_t)bx * BM * KDIM;

    const uint32_t swx     = (uint32_t)(lane & 7) << 4;
    const int a_mrow       = wm * 32 + (lane & 7) + ((lane >> 3) & 1) * 8;
    const uint32_t a_khalf = (uint32_t)(lane >> 4) * 16;
    const int b_nrow       = wn * 64 + (lane & 7) + ((lane >> 4) ? 8 : 0);
    const uint32_t b_khalf = (uint32_t)((lane >> 3) & 1) * 16;

    const int xr = tid >> 4;
    const int xc = tid & 15;

    float acc[2][8][4];
    #pragma unroll
    for (int i = 0; i < 2; i++)
        #pragma unroll
        for (int j = 0; j < 8; j++)
            #pragma unroll
            for (int q = 0; q < 4; q++) acc[i][j][q] = 0.0f;

    // ---- prologue: build chunk 0
    {
        char* ahi = sm + SM_BUF + OFF_AHI;
        char* alo = sm + SM_BUF + OFF_ALO;
        #pragma unroll
        for (int it = 0; it < 4; it++) {
            float4 v = *(const float4*)(Xblk + (size_t)(xr + it * 32) * KDIM + xc * 4);
            conv_store(v, ahi, alo, xr + it * 32, xc);
        }
        #pragma unroll
        for (int it = 0; it < 4; it++) {
            int id = tid + it * NTHR;
            int r = id >> 3, c = id & 7;
            uint32_t off = (uint32_t)(r * 128 + c * 16);
            uint32_t swo = off ^ ((off >> 3) & 0x70);
            cp_async16(smb + SM_BUF + OFF_B + swo, g_Wh + r * KDIM + c * 8);
        }
        cp_commit();
        cp_wait0();
        __syncthreads();
    }

    for (int kc = 0; kc < NCHUNK; kc++) {
        const uint32_t cur  = smb + SM_BUF + (uint32_t)(kc & 1) * BUF_BYTES;
        const uint32_t nxtb = smb + SM_BUF + (uint32_t)((kc & 1) ^ 1) * BUF_BYTES;
        char* nahi = sm + (nxtb - smb) + OFF_AHI;
        char* nalo = sm + (nxtb - smb) + OFF_ALO;
        const bool pre = (kc + 1 < NCHUNK);
        const int k0 = (kc + 1) * KC;

        float4 xv[4];

        #pragma unroll
        for (int kk = 0; kk < 4; kk++) {
            // ---- prefetch chunk kc+1, interleaved
            if (pre && kk == 0) {
                #pragma unroll
                for (int it = 0; it < 4; it++)
                    xv[it] = *(const float4*)(Xblk + (size_t)(xr + it * 32) * KDIM + k0 + xc * 4);
            }
            if (pre) {
                const int id = tid + kk * NTHR;
                const int r = id >> 3, c = id & 7;
                uint32_t off = (uint32_t)(r * 128 + c * 16);
                uint32_t swo = off ^ ((off >> 3) & 0x70);
                cp_async16(nxtb + OFF_B + swo, g_Wh + r * KDIM + k0 + c * 8);
            }

            // ---- ldmatrix + MMA for kk
            const uint32_t kof  = (uint32_t)(kk * 32);
            const uint32_t dynA = (kof + a_khalf) ^ swx;
            const uint32_t dynB = (kof + b_khalf) ^ swx;
            const uint32_t aHiB = cur + OFF_AHI + (uint32_t)(a_mrow * 128) + dynA;
            const uint32_t aLoB = cur + OFF_ALO + (uint32_t)(a_mrow * 128) + dynA;
            const uint32_t bB   = cur + OFF_B   + (uint32_t)(b_nrow * 128) + dynB;

            uint32_t ahi[2][4], alo[2][4];
            ldm_x4(aHiB,        ahi[0][0], ahi[0][1], ahi[0][2], ahi[0][3]);
            ldm_x4(aHiB + 2048, ahi[1][0], ahi[1][1], ahi[1][2], ahi[1][3]);
            ldm_x4(aLoB,        alo[0][0], alo[0][1], alo[0][2], alo[0][3]);
            ldm_x4(aLoB + 2048, alo[1][0], alo[1][1], alo[1][2], alo[1][3]);

            uint32_t bh[2][4];
            ldm_x4(bB, bh[0][0], bh[0][1], bh[0][2], bh[0][3]);

            #pragma unroll
            for (int ng = 0; ng < 4; ng++) {
                const int cb = ng & 1;
                if (ng < 3) {
                    const int nb = cb ^ 1;
                    ldm_x4(bB + (uint32_t)((ng + 1) * 2048),
                           bh[nb][0], bh[nb][1], bh[nb][2], bh[nb][3]);
                }
                mma16816(acc[0][2 * ng + 0], ahi[0], bh[cb][0], bh[cb][1]);
                mma16816(acc[0][2 * ng + 1], ahi[0], bh[cb][2], bh[cb][3]);
                mma16816(acc[1][2 * ng + 0], ahi[1], bh[cb][0], bh[cb][1]);
                mma16816(acc[1][2 * ng + 1], ahi[1], bh[cb][2], bh[cb][3]);
                mma16816(acc[0][2 * ng + 0], alo[0], bh[cb][0], bh[cb][1]);
                mma16816(acc[0][2 * ng + 1], alo[0], bh[cb][2], bh[cb][3]);
                mma16816(acc[1][2 * ng + 0], alo[1], bh[cb][0], bh[cb][1]);
                mma16816(acc[1][2 * ng + 1], alo[1], bh[cb][2], bh[cb][3]);
            }

            // ---- convert prefetched X into nxt A buffers
            if (pre && kk == 1) {
                conv_store(xv[0], nahi, nalo, xr,      xc);
                conv_store(xv[1], nahi, nalo, xr + 32, xc);
            }
            if (pre && kk == 2) {
                conv_store(xv[2], nahi, nalo, xr + 64, xc);
                conv_store(xv[3], nahi, nalo, xr + 96, xc);
            }
        }

        if (pre) {
            cp_commit();
            cp_wait0();
        }
        __syncthreads();
    }

    // ---- epilogue: bias + relu
    const float* sb = (const float*)(sm + SM_BIAS);
    const int mbase = bx * BM + wm * 32 + (lane >> 2);
    const int nbase = wn * 64 + (lane & 3) * 2;

    #pragma unroll
    for (int mb = 0; mb < 2; mb++) {
        #pragma unroll
        for (int nb = 0; nb < 8; nb++) {
            const int n = nbase + nb * 8;
            const float b0 = sb[n], b1 = sb[n + 1];
            const int m0 = mbase + mb * 16;
            float2 v0, v1;
            v0.x = fmaxf(acc[mb][nb][0] + b0, 0.0f);
            v0.y = fmaxf(acc[mb][nb][1] + b1, 0.0f);
            v1.x = fmaxf(acc[mb][nb][2] + b0, 0.0f);
            v1.y = fmaxf(acc[mb][nb][3] + b1, 0.0f);
            *(float2*)(out + (size_t)m0 * NDIM + n) = v0;
            *(float2*)(out + (size_t)(m0 + 8) * NDIM + n) = v1;
        }
    }
}

extern "C" void kernel_launch(void* const* d_in, const int* in_sizes, int n_in,
                              void* d_out, int out_size) {
    const float* X    = (const float*)d_in[0];
    const float* W    = (const float*)d_in[1];
    const float* bias = (const float*)d_in[2];
    float* out = (float*)d_out;

    cudaFuncSetAttribute(gemm_hmma_kernel,
                         cudaFuncAttributeMaxDynamicSharedMemorySize, SMEM_TOTAL);

    split_w_kernel<<<(NDIM * KDIM) / 256, 256>>>(W);

    const int Brows = in_sizes[0] / KDIM;
    gemm_hmma_kernel<<<Brows / BM, NTHR, SMEM_TOTAL>>>(X, bias, out);
}

// round 9
// speedup vs baseline: 4.5838x; 1.2617x over previous
#include <cuda_runtime.h>
#include <cuda_fp16.h>
#include <cstdint>

// relu(X[131072,256] @ W[256,256]^T + b), fp32.
// R7/R8: plain fp16 HGEMM — X = fp16(X), W = fp16(W), fp32 accumulate.
// Expected rel_err ~2.6e-4 (W-only fp16 measured 1.84e-4; X adds same in quadrature).
// (R8 = identical resubmission of R7 after GB300 container infra failure.)

#define KDIM 256
#define NDIM 256
#define BM   128
#define KC   64
#define NCHUNK (KDIM / KC)
#define NTHR 512

#define SM_BIAS  0
#define SM_BUF   1024
#define OFF_A    0          // 128 rows x 128B = 16KB
#define OFF_B    16384      // 256 rows x 128B = 32KB
#define BUF_BYTES 49152
#define SMEM_TOTAL (SM_BUF + 2 * BUF_BYTES)   // 99328

__device__ __forceinline__ uint32_t smem_u32(const void* p) {
    uint32_t a;
    asm("{ .reg .u64 t; cvta.to.shared.u64 t, %1; cvt.u32.u64 %0, t; }" : "=r"(a) : "l"(p));
    return a;
}

__device__ __forceinline__ void cp_async16(uint32_t dst, const void* src) {
    asm volatile("cp.async.cg.shared.global [%0], [%1], 16;" :: "r"(dst), "l"(src) : "memory");
}
__device__ __forceinline__ void cp_commit() {
    asm volatile("cp.async.commit_group;" ::: "memory");
}
__device__ __forceinline__ void cp_wait0() {
    asm volatile("cp.async.wait_group 0;" ::: "memory");
}

__device__ __forceinline__ void ldm_x4(uint32_t addr, uint32_t& r0, uint32_t& r1,
                                       uint32_t& r2, uint32_t& r3) {
    asm volatile("ldmatrix.sync.aligned.m8n8.x4.shared.b16 {%0,%1,%2,%3}, [%4];"
                 : "=r"(r0), "=r"(r1), "=r"(r2), "=r"(r3) : "r"(addr));
}

__device__ __forceinline__ void mma16816(float* c, const uint32_t* a, uint32_t b0, uint32_t b1) {
    asm volatile(
        "mma.sync.aligned.m16n8k16.row.col.f32.f16.f16.f32 "
        "{%0,%1,%2,%3}, {%4,%5,%6,%7}, {%8,%9}, {%0,%1,%2,%3};"
        : "+f"(c[0]), "+f"(c[1]), "+f"(c[2]), "+f"(c[3])
        : "r"(a[0]), "r"(a[1]), "r"(a[2]), "r"(a[3]), "r"(b0), "r"(b1));
}

__device__ __half g_Wh[NDIM * KDIM];

__global__ void split_w_kernel(const float* __restrict__ W) {
    int i = blockIdx.x * 256 + threadIdx.x;
    g_Wh[i] = __float2half_rn(W[i]);
}

// convert one float4 (4 K values) -> fp16 and store swizzled
__device__ __forceinline__ void conv_store(float4 v, char* abuf, int row, int c) {
    __half h0 = __float2half_rn(v.x);
    __half h1 = __float2half_rn(v.y);
    __half h2 = __float2half_rn(v.z);
    __half h3 = __float2half_rn(v.w);
    uint2 hv;
    hv.x = (uint32_t)__half_as_ushort(h0) | ((uint32_t)__half_as_ushort(h1) << 16);
    hv.y = (uint32_t)__half_as_ushort(h2) | ((uint32_t)__half_as_ushort(h3) << 16);
    uint32_t off = (uint32_t)(row * 128 + c * 8);
    uint32_t swo = off ^ ((off >> 3) & 0x70);
    *(uint2*)(abuf + swo) = hv;
}

__global__ __launch_bounds__(NTHR, 1)
void gemm_hmma_kernel(const float* __restrict__ X,
                      const float* __restrict__ bias,
                      float* __restrict__ out) {
    extern __shared__ char sm[];
    const uint32_t smb = smem_u32(sm);
    const int tid  = threadIdx.x;
    const int wid  = tid >> 5;
    const int lane = tid & 31;
    const int bx   = blockIdx.x;

    const int wm = wid & 3;        // M quarter (32 rows)
    const int wn = wid >> 2;       // N quarter (64 cols)

    if (tid < 256) ((float*)(sm + SM_BIAS))[tid] = bias[tid];

    const float* Xblk = X + (size_t)bx * BM * KDIM;

    const uint32_t swx     = (uint32_t)(lane & 7) << 4;
    const int a_mrow       = wm * 32 + (lane & 7) + ((lane >> 3) & 1) * 8;
    const uint32_t a_khalf = (uint32_t)(lane >> 4) * 16;
    const int b_nrow       = wn * 64 + (lane & 7) + ((lane >> 4) ? 8 : 0);
    const uint32_t b_khalf = (uint32_t)((lane >> 3) & 1) * 16;

    const int xr = tid >> 4;
    const int xc = tid & 15;

    float acc[2][8][4];
    #pragma unroll
    for (int i = 0; i < 2; i++)
        #pragma unroll
        for (int j = 0; j < 8; j++)
            #pragma unroll
            for (int q = 0; q < 4; q++) acc[i][j][q] = 0.0f;

    // ---- prologue: build chunk 0
    {
        char* abuf = sm + SM_BUF + OFF_A;
        #pragma unroll
        for (int it = 0; it < 4; it++) {
            float4 v = *(const float4*)(Xblk + (size_t)(xr + it * 32) * KDIM + xc * 4);
            conv_store(v, abuf, xr + it * 32, xc);
        }
        #pragma unroll
        for (int it = 0; it < 4; it++) {
            int id = tid + it * NTHR;
            int r = id >> 3, c = id & 7;
            uint32_t off = (uint32_t)(r * 128 + c * 16);
            uint32_t swo = off ^ ((off >> 3) & 0x70);
            cp_async16(smb + SM_BUF + OFF_B + swo, g_Wh + r * KDIM + c * 8);
        }
        cp_commit();
        cp_wait0();
        __syncthreads();
    }

    for (int kc = 0; kc < NCHUNK; kc++) {
        const uint32_t cur  = smb + SM_BUF + (uint32_t)(kc & 1) * BUF_BYTES;
        const uint32_t nxtb = smb + SM_BUF + (uint32_t)((kc & 1) ^ 1) * BUF_BYTES;
        char* nabuf = sm + (nxtb - smb) + OFF_A;
        const bool pre = (kc + 1 < NCHUNK);
        const int k0 = (kc + 1) * KC;

        float4 xv[4];

        #pragma unroll
        for (int kk = 0; kk < 4; kk++) {
            // ---- prefetch chunk kc+1, interleaved with MMA
            if (pre && kk == 0) {
                #pragma unroll
                for (int it = 0; it < 4; it++)
                    xv[it] = *(const float4*)(Xblk + (size_t)(xr + it * 32) * KDIM + k0 + xc * 4);
            }
            if (pre) {
                const int id = tid + kk * NTHR;
                const int r = id >> 3, c = id & 7;
                uint32_t off = (uint32_t)(r * 128 + c * 16);
                uint32_t swo = off ^ ((off >> 3) & 0x70);
                cp_async16(nxtb + OFF_B + swo, g_Wh + r * KDIM + k0 + c * 8);
            }

            // ---- ldmatrix + MMA for kk
            const uint32_t kof  = (uint32_t)(kk * 32);
            const uint32_t dynA = (kof + a_khalf) ^ swx;
            const uint32_t dynB = (kof + b_khalf) ^ swx;
            const uint32_t aB = cur + OFF_A + (uint32_t)(a_mrow * 128) + dynA;
            const uint32_t bB = cur + OFF_B + (uint32_t)(b_nrow * 128) + dynB;

            uint32_t ah[2][4];
            ldm_x4(aB,        ah[0][0], ah[0][1], ah[0][2], ah[0][3]);
            ldm_x4(aB + 2048, ah[1][0], ah[1][1], ah[1][2], ah[1][3]);

            uint32_t bh[2][4];
            ldm_x4(bB, bh[0][0], bh[0][1], bh[0][2], bh[0][3]);

            #pragma unroll
            for (int ng = 0; ng < 4; ng++) {
                const int cb = ng & 1;
                if (ng < 3) {
                    const int nb = cb ^ 1;
                    ldm_x4(bB + (uint32_t)((ng + 1) * 2048),
                           bh[nb][0], bh[nb][1], bh[nb][2], bh[nb][3]);
                }
                mma16816(acc[0][2 * ng + 0], ah[0], bh[cb][0], bh[cb][1]);
                mma16816(acc[0][2 * ng + 1], ah[0], bh[cb][2], bh[cb][3]);
                mma16816(acc[1][2 * ng + 0], ah[1], bh[cb][0], bh[cb][1]);
                mma16816(acc[1][2 * ng + 1], ah[1], bh[cb][2], bh[cb][3]);
            }

            // ---- convert prefetched X into nxt A buffer
            if (pre && kk == 1) {
                conv_store(xv[0], nabuf, xr,      xc);
                conv_store(xv[1], nabuf, xr + 32, xc);
            }
            if (pre && kk == 2) {
                conv_store(xv[2], nabuf, xr + 64, xc);
                conv_store(xv[3], nabuf, xr + 96, xc);
            }
        }

        if (pre) {
            cp_commit();
            cp_wait0();
        }
        __syncthreads();
    }

    // ---- epilogue: bias + relu
    const float* sb = (const float*)(sm + SM_BIAS);
    const int mbase = bx * BM + wm * 32 + (lane >> 2);
    const int nbase = wn * 64 + (lane & 3) * 2;

    #pragma unroll
    for (int mb = 0; mb < 2; mb++) {
        #pragma unroll
        for (int nb = 0; nb < 8; nb++) {
            const int n = nbase + nb * 8;
            const float b0 = sb[n], b1 = sb[n + 1];
            const int m0 = mbase + mb * 16;
            float2 v0, v1;
            v0.x = fmaxf(acc[mb][nb][0] + b0, 0.0f);
            v0.y = fmaxf(acc[mb][nb][1] + b1, 0.0f);
            v1.x = fmaxf(acc[mb][nb][2] + b0, 0.0f);
            v1.y = fmaxf(acc[mb][nb][3] + b1, 0.0f);
            *(float2*)(out + (size_t)m0 * NDIM + n) = v0;
            *(float2*)(out + (size_t)(m0 + 8) * NDIM + n) = v1;
        }
    }
}

extern "C" void kernel_launch(void* const* d_in, const int* in_sizes, int n_in,
                              void* d_out, int out_size) {
    const float* X    = (const float*)d_in[0];
    const float* W    = (const float*)d_in[1];
    const float* bias = (const float*)d_in[2];
    float* out = (float*)d_out;

    cudaFuncSetAttribute(gemm_hmma_kernel,
                         cudaFuncAttributeMaxDynamicSharedMemorySize, SMEM_TOTAL);

    split_w_kernel<<<(NDIM * KDIM) / 256, 256>>>(W);

    const int Brows = in_sizes[0] / KDIM;
    gemm_hmma_kernel<<<Brows / BM, NTHR, SMEM_TOTAL>>>(X, bias, out);
}

// round 10
// speedup vs baseline: 5.2791x; 1.1517x over previous
#include <cuda_runtime.h>
#include <cuda_fp16.h>
#include <cstdint>

// relu(X[131072,256] @ W[256,256]^T + b), fp32.
// R9: fp16 HGEMM; prefetch restructured so X LDG and B cp.async get a FULL
// chunk (~500cyc) of MMA latency cover. Convert + wait moved to chunk end.

#define KDIM 256
#define NDIM 256
#define BM   128
#define KC   64
#define NCHUNK (KDIM / KC)
#define NTHR 512

#define SM_BIAS  0
#define SM_BUF   1024
#define OFF_A    0          // 128 rows x 128B = 16KB
#define OFF_B    16384      // 256 rows x 128B = 32KB
#define BUF_BYTES 49152
#define SMEM_TOTAL (SM_BUF + 2 * BUF_BYTES)   // 99328

__device__ __forceinline__ uint32_t smem_u32(const void* p) {
    uint32_t a;
    asm("{ .reg .u64 t; cvta.to.shared.u64 t, %1; cvt.u32.u64 %0, t; }" : "=r"(a) : "l"(p));
    return a;
}

__device__ __forceinline__ void cp_async16(uint32_t dst, const void* src) {
    asm volatile("cp.async.cg.shared.global [%0], [%1], 16;" :: "r"(dst), "l"(src) : "memory");
}
__device__ __forceinline__ void cp_commit() {
    asm volatile("cp.async.commit_group;" ::: "memory");
}
__device__ __forceinline__ void cp_wait0() {
    asm volatile("cp.async.wait_group 0;" ::: "memory");
}

__device__ __forceinline__ void ldm_x4(uint32_t addr, uint32_t& r0, uint32_t& r1,
                                       uint32_t& r2, uint32_t& r3) {
    asm volatile("ldmatrix.sync.aligned.m8n8.x4.shared.b16 {%0,%1,%2,%3}, [%4];"
                 : "=r"(r0), "=r"(r1), "=r"(r2), "=r"(r3) : "r"(addr));
}

__device__ __forceinline__ void mma16816(float* c, const uint32_t* a, uint32_t b0, uint32_t b1) {
    asm volatile(
        "mma.sync.aligned.m16n8k16.row.col.f32.f16.f16.f32 "
        "{%0,%1,%2,%3}, {%4,%5,%6,%7}, {%8,%9}, {%0,%1,%2,%3};"
        : "+f"(c[0]), "+f"(c[1]), "+f"(c[2]), "+f"(c[3])
        : "r"(a[0]), "r"(a[1]), "r"(a[2]), "r"(a[3]), "r"(b0), "r"(b1));
}

__device__ __half g_Wh[NDIM * KDIM];

__global__ void split_w_kernel(const float* __restrict__ W) {
    int i = blockIdx.x * 256 + threadIdx.x;
    g_Wh[i] = __float2half_rn(W[i]);
}

// convert one float4 (4 K values) -> fp16 and store swizzled
__device__ __forceinline__ void conv_store(float4 v, char* abuf, int row, int c) {
    __half h0 = __float2half_rn(v.x);
    __half h1 = __float2half_rn(v.y);
    __half h2 = __float2half_rn(v.z);
    __half h3 = __float2half_rn(v.w);
    uint2 hv;
    hv.x = (uint32_t)__half_as_ushort(h0) | ((uint32_t)__half_as_ushort(h1) << 16);
    hv.y = (uint32_t)__half_as_ushort(h2) | ((uint32_t)__half_as_ushort(h3) << 16);
    uint32_t off = (uint32_t)(row * 128 + c * 8);
    uint32_t swo = off ^ ((off >> 3) & 0x70);
    *(uint2*)(abuf + swo) = hv;
}

__global__ __launch_bounds__(NTHR, 1)
void gemm_hmma_kernel(const float* __restrict__ X,
                      const float* __restrict__ bias,
                      float* __restrict__ out) {
    extern __shared__ char sm[];
    const uint32_t smb = smem_u32(sm);
    const int tid  = threadIdx.x;
    const int wid  = tid >> 5;
    const int lane = tid & 31;
    const int bx   = blockIdx.x;

    const int wm = wid & 3;        // M quarter (32 rows)
    const int wn = wid >> 2;       // N quarter (64 cols)

    if (tid < 256) ((float*)(sm + SM_BIAS))[tid] = bias[tid];

    const float* Xblk = X + (size_t)bx * BM * KDIM;

    const uint32_t swx     = (uint32_t)(lane & 7) << 4;
    const int a_mrow       = wm * 32 + (lane & 7) + ((lane >> 3) & 1) * 8;
    const uint32_t a_khalf = (uint32_t)(lane >> 4) * 16;
    const int b_nrow       = wn * 64 + (lane & 7) + ((lane >> 4) ? 8 : 0);
    const uint32_t b_khalf = (uint32_t)((lane >> 3) & 1) * 16;

    const int xr = tid >> 4;
    const int xc = tid & 15;
    // B cp.async coordinates (4 per thread)
    const int br = tid >> 3, bc = tid & 7;

    float acc[2][8][4];
    #pragma unroll
    for (int i = 0; i < 2; i++)
        #pragma unroll
        for (int j = 0; j < 8; j++)
            #pragma unroll
            for (int q = 0; q < 4; q++) acc[i][j][q] = 0.0f;

    // ---- prologue: build chunk 0
    {
        char* abuf = sm + SM_BUF + OFF_A;
        #pragma unroll
        for (int it = 0; it < 4; it++) {
            float4 v = *(const float4*)(Xblk + (size_t)(xr + it * 32) * KDIM + xc * 4);
            conv_store(v, abuf, xr + it * 32, xc);
        }
        #pragma unroll
        for (int it = 0; it < 4; it++) {
            int id = tid + it * NTHR;
            int r = id >> 3, c = id & 7;
            uint32_t off = (uint32_t)(r * 128 + c * 16);
            uint32_t swo = off ^ ((off >> 3) & 0x70);
            cp_async16(smb + SM_BUF + OFF_B + swo, g_Wh + r * KDIM + c * 8);
        }
        cp_commit();
        cp_wait0();
        __syncthreads();
    }

    for (int kc = 0; kc < NCHUNK; kc++) {
        const uint32_t cur  = smb + SM_BUF + (uint32_t)(kc & 1) * BUF_BYTES;
        const uint32_t nxtb = smb + SM_BUF + (uint32_t)((kc & 1) ^ 1) * BUF_BYTES;
        char* nabuf = sm + (nxtb - smb) + OFF_A;
        const bool pre = (kc + 1 < NCHUNK);
        const int k0 = (kc + 1) * KC;

        float4 xv[4];

        // ---- ALL prefetch for chunk kc+1 issued up front: full-chunk cover
        if (pre) {
            #pragma unroll
            for (int it = 0; it < 4; it++)
                xv[it] = *(const float4*)(Xblk + (size_t)(xr + it * 32) * KDIM + k0 + xc * 4);
            #pragma unroll
            for (int it = 0; it < 4; it++) {
                const int id = tid + it * NTHR;
                const int r = id >> 3, c = id & 7;
                uint32_t off = (uint32_t)(r * 128 + c * 16);
                uint32_t swo = off ^ ((off >> 3) & 0x70);
                cp_async16(nxtb + OFF_B + swo, g_Wh + r * KDIM + k0 + c * 8);
            }
            cp_commit();
        }

        // ---- clean MMA loop
        #pragma unroll
        for (int kk = 0; kk < 4; kk++) {
            const uint32_t kof  = (uint32_t)(kk * 32);
            const uint32_t dynA = (kof + a_khalf) ^ swx;
            const uint32_t dynB = (kof + b_khalf) ^ swx;
            const uint32_t aB = cur + OFF_A + (uint32_t)(a_mrow * 128) + dynA;
            const uint32_t bB = cur + OFF_B + (uint32_t)(b_nrow * 128) + dynB;

            uint32_t ah[2][4];
            ldm_x4(aB,        ah[0][0], ah[0][1], ah[0][2], ah[0][3]);
            ldm_x4(aB + 2048, ah[1][0], ah[1][1], ah[1][2], ah[1][3]);

            uint32_t bh[2][4];
            ldm_x4(bB, bh[0][0], bh[0][1], bh[0][2], bh[0][3]);

            #pragma unroll
            for (int ng = 0; ng < 4; ng++) {
                const int cb = ng & 1;
                if (ng < 3) {
                    const int nb = cb ^ 1;
                    ldm_x4(bB + (uint32_t)((ng + 1) * 2048),
                           bh[nb][0], bh[nb][1], bh[nb][2], bh[nb][3]);
                }
                mma16816(acc[0][2 * ng + 0], ah[0], bh[cb][0], bh[cb][1]);
                mma16816(acc[0][2 * ng + 1], ah[0], bh[cb][2], bh[cb][3]);
                mma16816(acc[1][2 * ng + 0], ah[1], bh[cb][0], bh[cb][1]);
                mma16816(acc[1][2 * ng + 1], ah[1], bh[cb][2], bh[cb][3]);
            }
        }

        // ---- chunk end: convert X (data long since arrived), wait B, barrier
        if (pre) {
            conv_store(xv[0], nabuf, xr,      xc);
            conv_store(xv[1], nabuf, xr + 32, xc);
            conv_store(xv[2], nabuf, xr + 64, xc);
            conv_store(xv[3], nabuf, xr + 96, xc);
            cp_wait0();
        }
        __syncthreads();
    }

    // ---- epilogue: bias + relu
    const float* sb = (const float*)(sm + SM_BIAS);
    const int mbase = bx * BM + wm * 32 + (lane >> 2);
    const int nbase = wn * 64 + (lane & 3) * 2;

    #pragma unroll
    for (int mb = 0; mb < 2; mb++) {
        #pragma unroll
        for (int nb = 0; nb < 8; nb++) {
            const int n = nbase + nb * 8;
            const float b0 = sb[n], b1 = sb[n + 1];
            const int m0 = mbase + mb * 16;
            float2 v0, v1;
            v0.x = fmaxf(acc[mb][nb][0] + b0, 0.0f);
            v0.y = fmaxf(acc[mb][nb][1] + b1, 0.0f);
            v1.x = fmaxf(acc[mb][nb][2] + b0, 0.0f);
            v1.y = fmaxf(acc[mb][nb][3] + b1, 0.0f);
            *(float2*)(out + (size_t)m0 * NDIM + n) = v0;
            *(float2*)(out + (size_t)(m0 + 8) * NDIM + n) = v1;
        }
    }
}

extern "C" void kernel_launch(void* const* d_in, const int* in_sizes, int n_in,
                              void* d_out, int out_size) {
    const float* X    = (const float*)d_in[0];
    const float* W    = (const float*)d_in[1];
    const float* bias = (const float*)d_in[2];
    float* out = (float*)d_out;

    cudaFuncSetAttribute(gemm_hmma_kernel,
                         cudaFuncAttributeMaxDynamicSharedMemorySize, SMEM_TOTAL);

    split_w_kernel<<<(NDIM * KDIM) / 256, 256>>>(W);

    const int Brows = in_sizes[0] / KDIM;
    gemm_hmma_kernel<<<Brows / BM, NTHR, SMEM_TOTAL>>>(X, bias, out);
}